// round 1
// baseline (speedup 1.0000x reference)
#include <cuda_runtime.h>
#include <math.h>

// Problem constants
#define B_SZ   8
#define S_LEN  2048
#define E_DIM  768
#define H_DIM  128
#define M_TOTAL (B_SZ * S_LEN)   // 16384 rows

// Scratch for projected q, k, v (allocation-free rule: __device__ globals)
__device__ float g_q[M_TOTAL * H_DIM];
__device__ float g_k[M_TOTAL * H_DIM];
__device__ float g_v[M_TOTAL * H_DIM];

// ---------------------------------------------------------------------------
// Kernel 1: QKV projection.  out[m][h] = sum_e (X[m][e] * mask[m]) * W[h][e]
// M=16384, N=128, K=768.  grid = (M/64, 3), block = 256.
// Per-thread micro-tile 8(m) x 4(n); n = lane + 32*j so b-loads from the
// pad-33 Ws tile are conflict-free (bank = lane + kk mod 32, all distinct).
// ---------------------------------------------------------------------------
#define BM 64
#define BK 32
#define XS_PAD 36
#define WS_PAD 33

__global__ __launch_bounds__(256, 2)
void qkv_kernel(const float* __restrict__ X,
                const float* __restrict__ mask,
                const float* __restrict__ Wq,
                const float* __restrict__ Wk,
                const float* __restrict__ Wv)
{
    __shared__ float Xs[BM][XS_PAD];
    __shared__ float Ws[H_DIM][WS_PAD];

    const int m0   = blockIdx.x * BM;
    const float* W = (blockIdx.y == 0) ? Wq : (blockIdx.y == 1 ? Wk : Wv);
    float* out     = (blockIdx.y == 0) ? g_q : (blockIdx.y == 1 ? g_k : g_v);

    const int tid  = threadIdx.x;
    const int lane = tid & 31;
    const int ty   = tid >> 5;       // 0..7 -> m rows ty*8 .. ty*8+7

    float acc[8][4];
#pragma unroll
    for (int i = 0; i < 8; i++)
#pragma unroll
        for (int j = 0; j < 4; j++) acc[i][j] = 0.f;

    for (int k0 = 0; k0 < E_DIM; k0 += BK) {
        // --- load X tile (64 x 32) with padding mask applied ---
#pragma unroll
        for (int i = 0; i < 2; i++) {
            int f   = tid + i * 256;        // 0..511, 8 float4 per row
            int row = f >> 3;
            int c4  = f & 7;
            float4 v = *(const float4*)&X[(size_t)(m0 + row) * E_DIM + k0 + c4 * 4];
            float mk = mask[m0 + row];
            Xs[row][c4 * 4 + 0] = v.x * mk;
            Xs[row][c4 * 4 + 1] = v.y * mk;
            Xs[row][c4 * 4 + 2] = v.z * mk;
            Xs[row][c4 * 4 + 3] = v.w * mk;
        }
        // --- load W tile (128 x 32) ---
#pragma unroll
        for (int i = 0; i < 4; i++) {
            int f   = tid + i * 256;        // 0..1023
            int row = f >> 3;
            int c4  = f & 7;
            float4 v = *(const float4*)&W[(size_t)row * E_DIM + k0 + c4 * 4];
            Ws[row][c4 * 4 + 0] = v.x;
            Ws[row][c4 * 4 + 1] = v.y;
            Ws[row][c4 * 4 + 2] = v.z;
            Ws[row][c4 * 4 + 3] = v.w;
        }
        __syncthreads();

#pragma unroll 8
        for (int kk = 0; kk < BK; kk++) {
            float a[8], b[4];
#pragma unroll
            for (int i = 0; i < 8; i++) a[i] = Xs[ty * 8 + i][kk];   // broadcast
#pragma unroll
            for (int j = 0; j < 4; j++) b[j] = Ws[lane + j * 32][kk]; // conflict-free
#pragma unroll
            for (int i = 0; i < 8; i++)
#pragma unroll
                for (int j = 0; j < 4; j++) acc[i][j] += a[i] * b[j];
        }
        __syncthreads();
    }

#pragma unroll
    for (int i = 0; i < 8; i++)
#pragma unroll
        for (int j = 0; j < 4; j++)
            out[(size_t)(m0 + ty * 8 + i) * H_DIM + lane + j * 32] = acc[i][j];
}

// ---------------------------------------------------------------------------
// Kernel 2: causal flash attention (fp32, online softmax).
// grid = (S/64, B), block = 256.  Thread t: ql = t>>2 (query in tile),
// dg = t&3 (dim slice of 32).  Q slice + O accumulator in registers,
// K/V tiles + score buffer in dynamic smem (82176 B).
// ---------------------------------------------------------------------------
#define QT 64
#define KT 64
#define SS_PAD 65

__global__ __launch_bounds__(256, 2)
void attn_kernel(float* __restrict__ out)
{
    extern __shared__ float sm[];
    float* Ks = sm;                    // 64 * 128
    float* Vs = sm + KT * H_DIM;       // 64 * 128
    float* Ss = sm + 2 * KT * H_DIM;   // 64 * 65

    const int b  = blockIdx.y;
    const int qt = blockIdx.x;
    const int q0 = qt * QT;
    const int tid = threadIdx.x;
    const int ql  = tid >> 2;          // 0..63
    const int dg  = tid & 3;           // dim group: dims dg*32 .. dg*32+31
    const float scale = 0.0883883476483184f;   // 1/sqrt(128)

    // Q slice into registers
    float qreg[32];
    {
        const float4* qp = (const float4*)&g_q[((size_t)b * S_LEN + q0 + ql) * H_DIM + dg * 32];
#pragma unroll
        for (int i = 0; i < 8; i++) {
            float4 t = qp[i];
            qreg[i * 4 + 0] = t.x; qreg[i * 4 + 1] = t.y;
            qreg[i * 4 + 2] = t.z; qreg[i * 4 + 3] = t.w;
        }
    }

    float oacc[32];
#pragma unroll
    for (int i = 0; i < 32; i++) oacc[i] = 0.f;
    float m_run = -1e30f, l_run = 0.f;

    const int ntiles = qt + 1;         // causal: kv tiles 0..qt
    for (int kt = 0; kt < ntiles; kt++) {
        const int k0 = kt * KT;
        __syncthreads();               // previous tile fully consumed
        // --- stage K and V tiles (each 64x128 = 2048 float4, 8 per thread) ---
#pragma unroll
        for (int i = 0; i < 8; i++) {
            int f   = tid + i * 256;   // 0..2047
            int row = f >> 5;          // 32 float4 per row
            int c4  = f & 31;
            size_t g = ((size_t)b * S_LEN + k0 + row) * H_DIM + c4 * 4;
            ((float4*)Ks)[f] = *(const float4*)&g_k[g];
            ((float4*)Vs)[f] = *(const float4*)&g_v[g];
        }
        __syncthreads();

        // --- pass 1: scores for this tile ---
        const bool diag = (kt == qt);
        float mt = -1e30f;
        for (int j = 0; j < KT; j++) {
            const float4* kr = (const float4*)&Ks[j * H_DIM + dg * 32];
            float p = 0.f;
#pragma unroll
            for (int i = 0; i < 8; i++) {
                float4 kv = kr[i];
                p += qreg[i * 4 + 0] * kv.x + qreg[i * 4 + 1] * kv.y
                   + qreg[i * 4 + 2] * kv.z + qreg[i * 4 + 3] * kv.w;
            }
            // reduce across the 4 dim-group lanes (same warp, lanes xor 1,2)
            p += __shfl_xor_sync(0xffffffffu, p, 1);
            p += __shfl_xor_sync(0xffffffffu, p, 2);
            p *= scale;
            if (diag && j > ql) p = -1e30f;   // causal mask on diagonal tile
            if (dg == 0) Ss[ql * SS_PAD + j] = p;
            mt = fmaxf(mt, p);
        }
        __syncwarp();                  // Ss producer/consumer are in same warp

        // --- rescale running state ---
        float m_new = fmaxf(m_run, mt);
        float corr  = __expf(m_run - m_new);
        l_run *= corr;
#pragma unroll
        for (int i = 0; i < 32; i++) oacc[i] *= corr;

        // --- pass 2: probabilities + PV accumulate ---
        for (int j = 0; j < KT; j++) {
            float p = __expf(Ss[ql * SS_PAD + j] - m_new);
            l_run += p;
            const float4* vr = (const float4*)&Vs[j * H_DIM + dg * 32];
#pragma unroll
            for (int i = 0; i < 8; i++) {
                float4 vv = vr[i];
                oacc[i * 4 + 0] += p * vv.x;
                oacc[i * 4 + 1] += p * vv.y;
                oacc[i * 4 + 2] += p * vv.z;
                oacc[i * 4 + 3] += p * vv.w;
            }
        }
        m_run = m_new;
    }

    // --- epilogue ---
    const float inv = 1.f / l_run;
    float4* op = (float4*)&out[((size_t)b * S_LEN + q0 + ql) * H_DIM + dg * 32];
#pragma unroll
    for (int i = 0; i < 8; i++) {
        float4 t;
        t.x = oacc[i * 4 + 0] * inv; t.y = oacc[i * 4 + 1] * inv;
        t.z = oacc[i * 4 + 2] * inv; t.w = oacc[i * 4 + 3] * inv;
        op[i] = t;
    }
}

// ---------------------------------------------------------------------------
extern "C" void kernel_launch(void* const* d_in, const int* in_sizes, int n_in,
                              void* d_out, int out_size)
{
    const float* X    = (const float*)d_in[0];   // [B,S,E]
    const float* mask = (const float*)d_in[1];   // [B,S]
    const float* Wq   = (const float*)d_in[2];   // [H,E]
    const float* Wk   = (const float*)d_in[3];
    const float* Wv   = (const float*)d_in[4];
    float* out        = (float*)d_out;           // [B,S,H]

    // QKV projection: 3 GEMMs
    dim3 g1(M_TOTAL / BM, 3);
    qkv_kernel<<<g1, 256>>>(X, mask, Wq, Wk, Wv);

    // Flash attention
    const int smem = (2 * KT * H_DIM + QT * SS_PAD) * (int)sizeof(float); // 82176
    static int attr_done = 0;
    if (!attr_done) {
        cudaFuncSetAttribute(attn_kernel,
                             cudaFuncAttributeMaxDynamicSharedMemorySize, smem);
        attr_done = 1;
    }
    dim3 g2(S_LEN / QT, B_SZ);
    attn_kernel<<<g2, 256, smem>>>(out);
}

// round 4
// speedup vs baseline: 6.8589x; 6.8589x over previous
#include <cuda_runtime.h>
#include <math.h>

// Problem constants
#define B_SZ   8
#define S_LEN  2048
#define E_DIM  768
#define H_DIM  128
#define M_TOTAL (B_SZ * S_LEN)   // 16384 rows

// Scratch for projected q, k, v (allocation-free rule: __device__ globals)
__device__ float g_q[M_TOTAL * H_DIM];
__device__ float g_k[M_TOTAL * H_DIM];
__device__ float g_v[M_TOTAL * H_DIM];

// ---------------------------------------------------------------------------
// Kernel 1: QKV projection.  out[m][h] = sum_e (X[m][e] * mask[m]) * W[h][e]
// M=16384, N=128, K=768.  grid = (M/64, 3), block = 256.
// float4-vectorized inner loop over k: 12 LDS.128 + 128 FFMA per kk4 step
// -> FMA-pipe bound.  Ws stride 36: lane-strided rows give 4-phase (minimal)
// wavefronts for the b loads.
// ---------------------------------------------------------------------------
#define BM 64
#define BK 32
#define XS_ST 36
#define WS_ST 36

__global__ __launch_bounds__(256, 2)
void qkv_kernel(const float* __restrict__ X,
                const float* __restrict__ mask,
                const float* __restrict__ Wq,
                const float* __restrict__ Wk,
                const float* __restrict__ Wv)
{
    __shared__ float Xs[BM * XS_ST];
    __shared__ float Ws[H_DIM * WS_ST];

    const int m0   = blockIdx.x * BM;
    const float* W = (blockIdx.y == 0) ? Wq : (blockIdx.y == 1 ? Wk : Wv);
    float* out     = (blockIdx.y == 0) ? g_q : (blockIdx.y == 1 ? g_k : g_v);

    const int tid  = threadIdx.x;
    const int lane = tid & 31;
    const int ty   = tid >> 5;       // 0..7 -> m rows ty*8 .. ty*8+7

    float acc[8][4];
#pragma unroll
    for (int i = 0; i < 8; i++)
#pragma unroll
        for (int j = 0; j < 4; j++) acc[i][j] = 0.f;

    for (int k0 = 0; k0 < E_DIM; k0 += BK) {
        // --- load X tile (64 x 32) with padding mask applied ---
#pragma unroll
        for (int i = 0; i < 2; i++) {
            int f   = tid + i * 256;        // 0..511, 8 float4 per row
            int row = f >> 3;
            int c4  = f & 7;
            float4 v = *(const float4*)&X[(size_t)(m0 + row) * E_DIM + k0 + c4 * 4];
            float mk = mask[m0 + row];
            float* d = &Xs[row * XS_ST + c4 * 4];
            d[0] = v.x * mk; d[1] = v.y * mk; d[2] = v.z * mk; d[3] = v.w * mk;
        }
        // --- load W tile (128 x 32) ---
#pragma unroll
        for (int i = 0; i < 4; i++) {
            int f   = tid + i * 256;        // 0..1023
            int row = f >> 3;
            int c4  = f & 7;
            float4 v = *(const float4*)&W[(size_t)row * E_DIM + k0 + c4 * 4];
            float* d = &Ws[row * WS_ST + c4 * 4];
            d[0] = v.x; d[1] = v.y; d[2] = v.z; d[3] = v.w;
        }
        __syncthreads();

#pragma unroll
        for (int kk4 = 0; kk4 < BK / 4; kk4++) {
            float4 a[8], b[4];
#pragma unroll
            for (int i = 0; i < 8; i++)
                a[i] = *(const float4*)&Xs[(ty * 8 + i) * XS_ST + kk4 * 4];
#pragma unroll
            for (int j = 0; j < 4; j++)
                b[j] = *(const float4*)&Ws[(lane + j * 32) * WS_ST + kk4 * 4];
#pragma unroll
            for (int i = 0; i < 8; i++)
#pragma unroll
                for (int j = 0; j < 4; j++) {
                    acc[i][j] += a[i].x * b[j].x;
                    acc[i][j] += a[i].y * b[j].y;
                    acc[i][j] += a[i].z * b[j].z;
                    acc[i][j] += a[i].w * b[j].w;
                }
        }
        __syncthreads();
    }

#pragma unroll
    for (int i = 0; i < 8; i++)
#pragma unroll
        for (int j = 0; j < 4; j++)
            out[(size_t)(m0 + ty * 8 + i) * H_DIM + lane + j * 32] = acc[i][j];
}

// ---------------------------------------------------------------------------
// Kernel 2: causal flash attention, register-tiled.
// grid = (32, 8), block = 256 = 16(tx) x 16(ty).
// Thread owns: S micro-tile 4x4 (m = ty+16i, n = tx+16j),
//              O micro-tile 4x8 (m = ty+16i, d = tx*4..+3 and 64+tx*4..+3).
// Smem: Qs/Ks/Vs stride 132 (bank-optimal for both row-strided float4 loads),
//       P  stride 80.
// ---------------------------------------------------------------------------
#define QT 64
#define KT 64
#define TS 132
#define PST 80

__global__ __launch_bounds__(256)
void attn_kernel(float* __restrict__ out)
{
    extern __shared__ float sm[];
    float* Qs = sm;                       // 64 * 132
    float* Ks = Qs + QT * TS;             // 64 * 132
    float* Vs = Ks + KT * TS;             // 64 * 132
    float* Pp = Vs + KT * TS;             // 64 * 80

    const int b   = blockIdx.y;
    const int qt  = (int)(gridDim.x - 1) - (int)blockIdx.x;  // long blocks first
    const int q0  = qt * QT;
    const int tid = threadIdx.x;
    const int tx  = tid & 15;
    const int ty  = tid >> 4;
    const float scale = 0.0883883476483184f;   // 1/sqrt(128)

    // --- stage Q tile (pre-scaled) ---
#pragma unroll
    for (int i = 0; i < 8; i++) {
        int f   = tid + i * 256;          // 0..2047
        int row = f >> 5;
        int c4  = f & 31;
        float4 v = *(const float4*)&g_q[((size_t)b * S_LEN + q0 + row) * H_DIM + c4 * 4];
        float* d = &Qs[row * TS + c4 * 4];
        d[0] = v.x * scale; d[1] = v.y * scale; d[2] = v.z * scale; d[3] = v.w * scale;
    }

    float oacc[4][8];
#pragma unroll
    for (int i = 0; i < 4; i++)
#pragma unroll
        for (int d = 0; d < 8; d++) oacc[i][d] = 0.f;
    float m_run[4] = {-1e30f, -1e30f, -1e30f, -1e30f};
    float l_run[4] = {0.f, 0.f, 0.f, 0.f};

    for (int kt = 0; kt <= qt; kt++) {
        const int k0 = kt * KT;
        __syncthreads();                  // prev tile fully consumed
        // --- stage K and V tiles ---
#pragma unroll
        for (int i = 0; i < 8; i++) {
            int f   = tid + i * 256;
            int row = f >> 5;
            int c4  = f & 31;
            size_t g = ((size_t)b * S_LEN + k0 + row) * H_DIM + c4 * 4;
            *(float4*)&Ks[row * TS + c4 * 4] = *(const float4*)&g_k[g];
            *(float4*)&Vs[row * TS + c4 * 4] = *(const float4*)&g_v[g];
        }
        __syncthreads();

        // --- S = Q K^T (register GEMM, 4x4 per thread) ---
        float s[4][4];
#pragma unroll
        for (int i = 0; i < 4; i++)
#pragma unroll
            for (int j = 0; j < 4; j++) s[i][j] = 0.f;

#pragma unroll 4
        for (int kk4 = 0; kk4 < H_DIM / 4; kk4++) {
            float4 a[4], bb[4];
#pragma unroll
            for (int i = 0; i < 4; i++)
                a[i] = *(const float4*)&Qs[(ty + 16 * i) * TS + kk4 * 4];
#pragma unroll
            for (int j = 0; j < 4; j++)
                bb[j] = *(const float4*)&Ks[(tx + 16 * j) * TS + kk4 * 4];
#pragma unroll
            for (int i = 0; i < 4; i++)
#pragma unroll
                for (int j = 0; j < 4; j++) {
                    s[i][j] += a[i].x * bb[j].x;
                    s[i][j] += a[i].y * bb[j].y;
                    s[i][j] += a[i].z * bb[j].z;
                    s[i][j] += a[i].w * bb[j].w;
                }
        }

        // --- causal mask on diagonal tile ---
        if (kt == qt) {
#pragma unroll
            for (int i = 0; i < 4; i++)
#pragma unroll
                for (int j = 0; j < 4; j++)
                    if (tx + 16 * j > ty + 16 * i) s[i][j] = -1e30f;
        }

        // --- online softmax: row reduce over 16 tx lanes (same half-warp) ---
#pragma unroll
        for (int i = 0; i < 4; i++) {
            float mt = fmaxf(fmaxf(s[i][0], s[i][1]), fmaxf(s[i][2], s[i][3]));
            mt = fmaxf(mt, __shfl_xor_sync(0xffffffffu, mt, 1));
            mt = fmaxf(mt, __shfl_xor_sync(0xffffffffu, mt, 2));
            mt = fmaxf(mt, __shfl_xor_sync(0xffffffffu, mt, 4));
            mt = fmaxf(mt, __shfl_xor_sync(0xffffffffu, mt, 8));
            float m_new = fmaxf(m_run[i], mt);
            float rs = 0.f;
#pragma unroll
            for (int j = 0; j < 4; j++) {
                float p = __expf(s[i][j] - m_new);
                Pp[(ty + 16 * i) * PST + tx + 16 * j] = p;
                rs += p;
            }
            rs += __shfl_xor_sync(0xffffffffu, rs, 1);
            rs += __shfl_xor_sync(0xffffffffu, rs, 2);
            rs += __shfl_xor_sync(0xffffffffu, rs, 4);
            rs += __shfl_xor_sync(0xffffffffu, rs, 8);
            float corr = __expf(m_run[i] - m_new);
            l_run[i] = l_run[i] * corr + rs;
            m_run[i] = m_new;
#pragma unroll
            for (int d = 0; d < 8; d++) oacc[i][d] *= corr;
        }
        __syncthreads();                  // Pp visible to all warps

        // --- O += P V (register GEMM, 4(m) x 8(d) per thread) ---
#pragma unroll 4
        for (int j = 0; j < KT; j++) {
            float pr[4];
#pragma unroll
            for (int i = 0; i < 4; i++)
                pr[i] = Pp[(ty + 16 * i) * PST + j];
            float4 v0 = *(const float4*)&Vs[j * TS + tx * 4];
            float4 v1 = *(const float4*)&Vs[j * TS + 64 + tx * 4];
#pragma unroll
            for (int i = 0; i < 4; i++) {
                oacc[i][0] += pr[i] * v0.x;
                oacc[i][1] += pr[i] * v0.y;
                oacc[i][2] += pr[i] * v0.z;
                oacc[i][3] += pr[i] * v0.w;
                oacc[i][4] += pr[i] * v1.x;
                oacc[i][5] += pr[i] * v1.y;
                oacc[i][6] += pr[i] * v1.z;
                oacc[i][7] += pr[i] * v1.w;
            }
        }
    }

    // --- epilogue ---
#pragma unroll
    for (int i = 0; i < 4; i++) {
        float inv = 1.f / l_run[i];
        size_t base = ((size_t)b * S_LEN + q0 + ty + 16 * i) * H_DIM;
        float4 t0, t1;
        t0.x = oacc[i][0] * inv; t0.y = oacc[i][1] * inv;
        t0.z = oacc[i][2] * inv; t0.w = oacc[i][3] * inv;
        t1.x = oacc[i][4] * inv; t1.y = oacc[i][5] * inv;
        t1.z = oacc[i][6] * inv; t1.w = oacc[i][7] * inv;
        *(float4*)&out[base + tx * 4]      = t0;
        *(float4*)&out[base + 64 + tx * 4] = t1;
    }
}

// ---------------------------------------------------------------------------
extern "C" void kernel_launch(void* const* d_in, const int* in_sizes, int n_in,
                              void* d_out, int out_size)
{
    const float* X    = (const float*)d_in[0];   // [B,S,E]
    const float* mask = (const float*)d_in[1];   // [B,S]
    const float* Wq   = (const float*)d_in[2];   // [H,E]
    const float* Wk   = (const float*)d_in[3];
    const float* Wv   = (const float*)d_in[4];
    float* out        = (float*)d_out;           // [B,S,H]

    // QKV projection: 3 GEMMs
    dim3 g1(M_TOTAL / BM, 3);
    qkv_kernel<<<g1, 256>>>(X, mask, Wq, Wk, Wv);

    // Flash attention
    const int smem = (3 * KT * TS + QT * PST) * (int)sizeof(float); // 121856 B
    cudaFuncSetAttribute(attn_kernel,
                         cudaFuncAttributeMaxDynamicSharedMemorySize, smem);
    dim3 g2(S_LEN / QT, B_SZ);
    attn_kernel<<<g2, 256, smem>>>(out);
}

// round 8
// speedup vs baseline: 12.1942x; 1.7779x over previous
#include <cuda_runtime.h>
#include <cuda_bf16.h>
#include <cstdint>

#define B_SZ   8
#define S_LEN  2048
#define E_DIM  768
#define H_DIM  128
#define M_TOTAL (B_SZ * S_LEN)

// hi/lo bf16 split q, k, v (q pre-scaled by 1/sqrt(128)), row-major [b*S+s][d]
__device__ __nv_bfloat16 g_qh[M_TOTAL * H_DIM];
__device__ __nv_bfloat16 g_ql[M_TOTAL * H_DIM];
__device__ __nv_bfloat16 g_kh[M_TOTAL * H_DIM];
__device__ __nv_bfloat16 g_kl[M_TOTAL * H_DIM];
__device__ __nv_bfloat16 g_vh[M_TOTAL * H_DIM];
__device__ __nv_bfloat16 g_vl[M_TOTAL * H_DIM];

// ---------------------------------------------------------------------------
// helpers (baseline PTX only: mma.sync + ldmatrix, no tcgen05)
// ---------------------------------------------------------------------------
__device__ __forceinline__ uint32_t smem_u32(const void* p) {
    uint32_t a;
    asm("{ .reg .u64 t; cvta.to.shared.u64 t, %1; cvt.u32.u64 %0, t; }"
        : "=r"(a) : "l"(p));
    return a;
}

__device__ __forceinline__ void mma16816(float c[4],
                                         uint32_t a0, uint32_t a1, uint32_t a2, uint32_t a3,
                                         uint32_t b0, uint32_t b1) {
    asm volatile(
        "mma.sync.aligned.m16n8k16.row.col.f32.bf16.bf16.f32 "
        "{%0,%1,%2,%3}, {%4,%5,%6,%7}, {%8,%9}, {%0,%1,%2,%3};"
        : "+f"(c[0]), "+f"(c[1]), "+f"(c[2]), "+f"(c[3])
        : "r"(a0), "r"(a1), "r"(a2), "r"(a3), "r"(b0), "r"(b1));
}

__device__ __forceinline__ void ldmx4(uint32_t r[4], uint32_t addr) {
    asm volatile("ldmatrix.sync.aligned.m8n8.x4.shared.b16 {%0,%1,%2,%3}, [%4];"
                 : "=r"(r[0]), "=r"(r[1]), "=r"(r[2]), "=r"(r[3]) : "r"(addr));
}
__device__ __forceinline__ void ldmx2t(uint32_t& r0, uint32_t& r1, uint32_t addr) {
    asm volatile("ldmatrix.sync.aligned.m8n8.x2.trans.shared.b16 {%0,%1}, [%2];"
                 : "=r"(r0), "=r"(r1) : "r"(addr));
}

// hi/lo bf16 split of two floats packed bf16x2 (first value in low half)
__device__ __forceinline__ void split2(float a, float b, uint32_t& hi, uint32_t& lo) {
    __nv_bfloat16 ah = __float2bfloat16(a);
    __nv_bfloat16 bh = __float2bfloat16(b);
    __nv_bfloat16 al = __float2bfloat16(a - __bfloat162float(ah));
    __nv_bfloat16 bl = __float2bfloat16(b - __bfloat162float(bh));
    hi = ((uint32_t)__bfloat16_as_ushort(bh) << 16) | (uint32_t)__bfloat16_as_ushort(ah);
    lo = ((uint32_t)__bfloat16_as_ushort(bl) << 16) | (uint32_t)__bfloat16_as_ushort(al);
}

// ---------------------------------------------------------------------------
// Kernel 1: QKV projection, bf16x3 warp MMA.
// grid=(256, 3), block=128 (4 warps x 16 m-rows).  BM=64, BN=128, BK=64.
// smem (bytes): Xh 0..9216, Xl ..18432, Wh ..36864, Wl ..55296 (strides 72 bf16).
// ---------------------------------------------------------------------------
#define QAST 72
#define QKV_SMEM 55296

__global__ __launch_bounds__(128)
void qkv_mma_kernel(const float* __restrict__ X, const float* __restrict__ mask,
                    const float* __restrict__ Wq, const float* __restrict__ Wk,
                    const float* __restrict__ Wv)
{
    extern __shared__ __align__(16) char sm_[];
    __nv_bfloat16* Xh = (__nv_bfloat16*)sm_;                 // [64][72]
    __nv_bfloat16* Wh = (__nv_bfloat16*)(sm_ + 18432);       // [128][72]

    const int tid  = threadIdx.x;
    const int lane = tid & 31;
    const int wid  = tid >> 5;
    const int m0   = blockIdx.x * 64;
    const int o    = blockIdx.y;
    const float* W = (o == 0) ? Wq : (o == 1 ? Wk : Wv);

    float c[16][4];
#pragma unroll
    for (int j = 0; j < 16; j++)
#pragma unroll
        for (int i = 0; i < 4; i++) c[j][i] = 0.f;

    const uint32_t xh_base = smem_u32(Xh);

    for (int k0 = 0; k0 < E_DIM; k0 += 64) {
        if (k0) __syncthreads();
        // --- stage X chunk [64 x 64] fp32 -> hi/lo bf16 (mask folded) ---
#pragma unroll
        for (int i = 0; i < 8; i++) {
            int idx = tid + i * 128;           // 0..1023 float4
            int row = idx >> 4, c4 = idx & 15;
            float mk = mask[m0 + row];
            float4 v = *(const float4*)&X[(size_t)(m0 + row) * E_DIM + k0 + c4 * 4];
            uint32_t h0, l0, h1, l1;
            split2(v.x * mk, v.y * mk, h0, l0);
            split2(v.z * mk, v.w * mk, h1, l1);
            *(uint2*)&Xh[row * QAST + c4 * 4]        = make_uint2(h0, h1);
            *(uint2*)&Xh[4608 + row * QAST + c4 * 4] = make_uint2(l0, l1);  // Xl = Xh + 4608 elems
        }
        // --- stage W chunk [128 x 64] ---
#pragma unroll
        for (int i = 0; i < 16; i++) {
            int idx = tid + i * 128;           // 0..2047 float4
            int row = idx >> 4, c4 = idx & 15;
            float4 v = *(const float4*)&W[(size_t)row * E_DIM + k0 + c4 * 4];
            uint32_t h0, l0, h1, l1;
            split2(v.x, v.y, h0, l0);
            split2(v.z, v.w, h1, l1);
            *(uint2*)&Wh[row * QAST + c4 * 4]        = make_uint2(h0, h1);
            *(uint2*)&Wh[9216 + row * QAST + c4 * 4] = make_uint2(l0, l1);  // Wl = Wh + 9216 elems
        }
        __syncthreads();

#pragma unroll
        for (int kd = 0; kd < 4; kd++) {
            uint32_t ah[4], al[4];
            uint32_t aaddr = xh_base +
                ((wid * 16 + (lane & 15)) * QAST + kd * 16 + ((lane >> 4) << 3)) * 2;
            ldmx4(ah, aaddr);
            ldmx4(al, aaddr + 9216);           // Xl byte offset
#pragma unroll
            for (int j = 0; j < 16; j++) {
                const __nv_bfloat16* bp =
                    &Wh[(j * 8 + (lane >> 2)) * QAST + kd * 16 + (lane & 3) * 2];
                uint32_t bh0 = *(const uint32_t*)bp;
                uint32_t bh1 = *(const uint32_t*)(bp + 8);
                uint32_t bl0 = *(const uint32_t*)(bp + 9216);
                uint32_t bl1 = *(const uint32_t*)(bp + 9224);
                mma16816(c[j], ah[0], ah[1], ah[2], ah[3], bh0, bh1);
                mma16816(c[j], ah[0], ah[1], ah[2], ah[3], bl0, bl1);
                mma16816(c[j], al[0], al[1], al[2], al[3], bh0, bh1);
            }
        }
    }

    // --- epilogue: split to hi/lo bf16 ---
    const float sc = (o == 0) ? 0.0883883476483184f : 1.f;   // 1/sqrt(128) on q
    __nv_bfloat16* oh = (o == 0) ? g_qh : (o == 1 ? g_kh : g_vh);
    __nv_bfloat16* ol = (o == 0) ? g_ql : (o == 1 ? g_kl : g_vl);
    const int grp = lane >> 2;
    const size_t r0 = (size_t)(m0 + wid * 16 + grp) * H_DIM;
    const size_t r1 = r0 + 8 * H_DIM;
#pragma unroll
    for (int j = 0; j < 16; j++) {
        int col = j * 8 + (lane & 3) * 2;
        uint32_t h, l;
        split2(c[j][0] * sc, c[j][1] * sc, h, l);
        *(uint32_t*)&oh[r0 + col] = h;
        *(uint32_t*)&ol[r0 + col] = l;
        split2(c[j][2] * sc, c[j][3] * sc, h, l);
        *(uint32_t*)&oh[r1 + col] = h;
        *(uint32_t*)&ol[r1 + col] = l;
    }
}

// ---------------------------------------------------------------------------
// Kernel 2: causal flash attention, bf16x3 warp MMA.
// grid=(32, 8) (long diagonals first), block=128 (4 warps x 16 q-rows).
// QT=KT=64.  S C-frags double as PV A-frags (in-register P, no smem round-trip).
// smem bf16 elems (stride 136): Qh 0, Ql 8704, Kh 17408, Kl 26112, Vh 34816,
// Vl 43520; total 104448 bytes -> 2 CTAs/SM.
// ---------------------------------------------------------------------------
#define AST 136
#define ATT_SMEM 104448

__global__ __launch_bounds__(128)
void attn_mma_kernel(float* __restrict__ out)
{
    extern __shared__ __align__(16) char sm_[];
    __nv_bfloat16* Qh = (__nv_bfloat16*)sm_;
    __nv_bfloat16* Kh = Qh + 17408;
    __nv_bfloat16* Vh = Qh + 34816;

    const int tid  = threadIdx.x;
    const int lane = tid & 31;
    const int wid  = tid >> 5;
    const int b    = blockIdx.y;
    const int qt   = 31 - (int)blockIdx.x;     // long blocks first
    const int q0   = qt * 64;

    const uint32_t qh_base = smem_u32(Qh);
    const uint32_t kh_base = smem_u32(Kh);
    const uint32_t vh_base = smem_u32(Vh);

    // --- stage Q (hi/lo), persists across kv tiles ---
#pragma unroll
    for (int i = 0; i < 8; i++) {
        int idx = tid + i * 128;               // 0..1023 uint4 (8 bf16)
        int row = idx >> 4, c8 = idx & 15;
        size_t g = ((size_t)b * S_LEN + q0 + row) * H_DIM + c8 * 8;
        *(uint4*)&Qh[row * AST + c8 * 8]        = *(const uint4*)&g_qh[g];
        *(uint4*)&Qh[8704 + row * AST + c8 * 8] = *(const uint4*)&g_ql[g];
    }

    float o_[16][4];
#pragma unroll
    for (int d = 0; d < 16; d++)
#pragma unroll
        for (int i = 0; i < 4; i++) o_[d][i] = 0.f;
    float lsum0 = 0.f, lsum1 = 0.f;

    const int grp  = lane >> 2;
    const int colb = (lane & 3) * 2;
    const int r0l  = wid * 16 + grp;           // local q row of c0/c1
    const int r1l  = r0l + 8;

    for (int kt = 0; kt <= qt; kt++) {
        const int k0 = kt * 64;
        __syncthreads();
        // --- stage K, V hi/lo tiles [64 x 128] ---
#pragma unroll
        for (int i = 0; i < 8; i++) {
            int idx = tid + i * 128;
            int row = idx >> 4, c8 = idx & 15;
            size_t g = ((size_t)b * S_LEN + k0 + row) * H_DIM + c8 * 8;
            int so = row * AST + c8 * 8;
            *(uint4*)&Kh[so]        = *(const uint4*)&g_kh[g];
            *(uint4*)&Kh[8704 + so] = *(const uint4*)&g_kl[g];
            *(uint4*)&Vh[so]        = *(const uint4*)&g_vh[g];
            *(uint4*)&Vh[8704 + so] = *(const uint4*)&g_vl[g];
        }
        __syncthreads();

        // --- S = Q K^T  (A = Q ldmatrix, B = K direct LDS: [n][d] is col-major) ---
        float s[8][4];
#pragma unroll
        for (int j = 0; j < 8; j++)
#pragma unroll
            for (int i = 0; i < 4; i++) s[j][i] = 0.f;

#pragma unroll
        for (int kd = 0; kd < 8; kd++) {
            uint32_t ah[4], al[4];
            uint32_t aaddr = qh_base +
                ((wid * 16 + (lane & 15)) * AST + kd * 16 + ((lane >> 4) << 3)) * 2;
            ldmx4(ah, aaddr);
            ldmx4(al, aaddr + 17408);
#pragma unroll
            for (int j = 0; j < 8; j++) {
                const __nv_bfloat16* bp =
                    &Kh[(j * 8 + (lane >> 2)) * AST + kd * 16 + (lane & 3) * 2];
                uint32_t bh0 = *(const uint32_t*)bp;
                uint32_t bh1 = *(const uint32_t*)(bp + 8);
                uint32_t bl0 = *(const uint32_t*)(bp + 8704);
                uint32_t bl1 = *(const uint32_t*)(bp + 8712);
                mma16816(s[j], ah[0], ah[1], ah[2], ah[3], bh0, bh1);
                mma16816(s[j], ah[0], ah[1], ah[2], ah[3], bl0, bl1);
                mma16816(s[j], al[0], al[1], al[2], al[3], bh0, bh1);
            }
        }

        // --- exp (+ causal mask on diagonal tile), row sums ---
        const bool diag = (kt == qt);
        float rs0 = 0.f, rs1 = 0.f;
#pragma unroll
        for (int j = 0; j < 8; j++) {
            int cc = j * 8 + colb;
            float e0 = __expf(s[j][0]);
            float e1 = __expf(s[j][1]);
            float e2 = __expf(s[j][2]);
            float e3 = __expf(s[j][3]);
            if (diag) {
                if (cc     > r0l) e0 = 0.f;
                if (cc + 1 > r0l) e1 = 0.f;
                if (cc     > r1l) e2 = 0.f;
                if (cc + 1 > r1l) e3 = 0.f;
            }
            s[j][0] = e0; s[j][1] = e1; s[j][2] = e2; s[j][3] = e3;
            rs0 += e0 + e1;
            rs1 += e2 + e3;
        }
        rs0 += __shfl_xor_sync(0xffffffffu, rs0, 1);
        rs0 += __shfl_xor_sync(0xffffffffu, rs0, 2);
        rs1 += __shfl_xor_sync(0xffffffffu, rs1, 1);
        rs1 += __shfl_xor_sync(0xffffffffu, rs1, 2);
        lsum0 += rs0;
        lsum1 += rs1;

        // --- O += P V.  P A-frags built in-register from S C-frags. ---
#pragma unroll
        for (int j2 = 0; j2 < 4; j2++) {
            uint32_t ph[4], pl[4];
            split2(s[2 * j2][0],     s[2 * j2][1],     ph[0], pl[0]);
            split2(s[2 * j2][2],     s[2 * j2][3],     ph[1], pl[1]);
            split2(s[2 * j2 + 1][0], s[2 * j2 + 1][1], ph[2], pl[2]);
            split2(s[2 * j2 + 1][2], s[2 * j2 + 1][3], ph[3], pl[3]);
#pragma unroll
            for (int dn = 0; dn < 16; dn++) {
                uint32_t vaddr = vh_base +
                    ((j2 * 16 + (lane & 15)) * AST + dn * 8) * 2;
                uint32_t vh0, vh1, vl0, vl1;
                ldmx2t(vh0, vh1, vaddr);
                ldmx2t(vl0, vl1, vaddr + 17408);
                mma16816(o_[dn], ph[0], ph[1], ph[2], ph[3], vh0, vh1);
                mma16816(o_[dn], ph[0], ph[1], ph[2], ph[3], vl0, vl1);
                mma16816(o_[dn], pl[0], pl[1], pl[2], pl[3], vh0, vh1);
            }
        }
    }

    // --- epilogue ---
    const float inv0 = 1.f / lsum0;
    const float inv1 = 1.f / lsum1;
    const size_t gr0 = ((size_t)b * S_LEN + q0 + r0l) * H_DIM;
    const size_t gr1 = gr0 + 8 * H_DIM;
#pragma unroll
    for (int dn = 0; dn < 16; dn++) {
        int col = dn * 8 + colb;
        *(float2*)&out[gr0 + col] = make_float2(o_[dn][0] * inv0, o_[dn][1] * inv0);
        *(float2*)&out[gr1 + col] = make_float2(o_[dn][2] * inv1, o_[dn][3] * inv1);
    }
}

// ---------------------------------------------------------------------------
extern "C" void kernel_launch(void* const* d_in, const int* in_sizes, int n_in,
                              void* d_out, int out_size)
{
    const float* X    = (const float*)d_in[0];
    const float* mask = (const float*)d_in[1];
    const float* Wq   = (const float*)d_in[2];
    const float* Wk   = (const float*)d_in[3];
    const float* Wv   = (const float*)d_in[4];
    float* out        = (float*)d_out;

    cudaFuncSetAttribute(qkv_mma_kernel,
                         cudaFuncAttributeMaxDynamicSharedMemorySize, QKV_SMEM);
    dim3 g1(M_TOTAL / 64, 3);
    qkv_mma_kernel<<<g1, 128, QKV_SMEM>>>(X, mask, Wq, Wk, Wv);

    cudaFuncSetAttribute(attn_mma_kernel,
                         cudaFuncAttributeMaxDynamicSharedMemorySize, ATT_SMEM);
    dim3 g2(32, B_SZ);
    attn_mma_kernel<<<g2, 128, ATT_SMEM>>>(out);
}

// round 9
// speedup vs baseline: 16.9695x; 1.3916x over previous
#include <cuda_runtime.h>
#include <cuda_bf16.h>
#include <cstdint>

#define B_SZ   8
#define S_LEN  2048
#define E_DIM  768
#define H_DIM  128
#define M_TOTAL (B_SZ * S_LEN)

// hi/lo bf16 split inputs (produced by split kernels)
__device__ __nv_bfloat16 g_xh[M_TOTAL * E_DIM];
__device__ __nv_bfloat16 g_xl[M_TOTAL * E_DIM];
__device__ __nv_bfloat16 g_wh[3 * H_DIM * E_DIM];
__device__ __nv_bfloat16 g_wl[3 * H_DIM * E_DIM];
// hi/lo bf16 split q, k, v (q pre-scaled by 1/sqrt(128)), row-major
__device__ __nv_bfloat16 g_qh[M_TOTAL * H_DIM];
__device__ __nv_bfloat16 g_ql[M_TOTAL * H_DIM];
__device__ __nv_bfloat16 g_kh[M_TOTAL * H_DIM];
__device__ __nv_bfloat16 g_kl[M_TOTAL * H_DIM];
__device__ __nv_bfloat16 g_vh[M_TOTAL * H_DIM];
__device__ __nv_bfloat16 g_vl[M_TOTAL * H_DIM];

// ---------------------------------------------------------------------------
// helpers (baseline PTX only: mma.sync + ldmatrix + cp.async)
// ---------------------------------------------------------------------------
__device__ __forceinline__ uint32_t smem_u32(const void* p) {
    uint32_t a;
    asm("{ .reg .u64 t; cvta.to.shared.u64 t, %1; cvt.u32.u64 %0, t; }"
        : "=r"(a) : "l"(p));
    return a;
}
__device__ __forceinline__ void mma16816(float c[4],
                                         uint32_t a0, uint32_t a1, uint32_t a2, uint32_t a3,
                                         uint32_t b0, uint32_t b1) {
    asm volatile(
        "mma.sync.aligned.m16n8k16.row.col.f32.bf16.bf16.f32 "
        "{%0,%1,%2,%3}, {%4,%5,%6,%7}, {%8,%9}, {%0,%1,%2,%3};"
        : "+f"(c[0]), "+f"(c[1]), "+f"(c[2]), "+f"(c[3])
        : "r"(a0), "r"(a1), "r"(a2), "r"(a3), "r"(b0), "r"(b1));
}
__device__ __forceinline__ void ldmx4(uint32_t r[4], uint32_t addr) {
    asm volatile("ldmatrix.sync.aligned.m8n8.x4.shared.b16 {%0,%1,%2,%3}, [%4];"
                 : "=r"(r[0]), "=r"(r[1]), "=r"(r[2]), "=r"(r[3]) : "r"(addr));
}
__device__ __forceinline__ void ldmx2t(uint32_t& r0, uint32_t& r1, uint32_t addr) {
    asm volatile("ldmatrix.sync.aligned.m8n8.x2.trans.shared.b16 {%0,%1}, [%2];"
                 : "=r"(r0), "=r"(r1) : "r"(addr));
}
__device__ __forceinline__ void cp16(uint32_t s, const void* g) {
    asm volatile("cp.async.cg.shared.global [%0], [%1], 16;" :: "r"(s), "l"(g));
}
#define CP_COMMIT()  asm volatile("cp.async.commit_group;" ::: "memory")
#define CP_WAIT1()   asm volatile("cp.async.wait_group 1;" ::: "memory")
#define CP_WAIT0()   asm volatile("cp.async.wait_group 0;" ::: "memory")

// hi/lo bf16 split of two floats packed bf16x2 (first value in low half)
__device__ __forceinline__ void split2(float a, float b, uint32_t& hi, uint32_t& lo) {
    __nv_bfloat16 ah = __float2bfloat16(a);
    __nv_bfloat16 bh = __float2bfloat16(b);
    __nv_bfloat16 al = __float2bfloat16(a - __bfloat162float(ah));
    __nv_bfloat16 bl = __float2bfloat16(b - __bfloat162float(bh));
    hi = ((uint32_t)__bfloat16_as_ushort(bh) << 16) | (uint32_t)__bfloat16_as_ushort(ah);
    lo = ((uint32_t)__bfloat16_as_ushort(bl) << 16) | (uint32_t)__bfloat16_as_ushort(al);
}

// ---------------------------------------------------------------------------
// Kernel 0a/0b: one-time hi/lo splits (memory-bound)
// ---------------------------------------------------------------------------
__global__ __launch_bounds__(256)
void split_x_kernel(const float* __restrict__ X, const float* __restrict__ mask)
{
    int idx = (blockIdx.x * 256 + threadIdx.x) * 4;
    float mk = mask[idx / E_DIM];
    float4 v = *(const float4*)&X[idx];
    uint32_t h0, l0, h1, l1;
    split2(v.x * mk, v.y * mk, h0, l0);
    split2(v.z * mk, v.w * mk, h1, l1);
    *(uint2*)&g_xh[idx] = make_uint2(h0, h1);
    *(uint2*)&g_xl[idx] = make_uint2(l0, l1);
}
__global__ __launch_bounds__(256)
void split_w_kernel(const float* __restrict__ Wq, const float* __restrict__ Wk,
                    const float* __restrict__ Wv)
{
    int idx = (blockIdx.x * 256 + threadIdx.x) * 4;
    int o = idx / (H_DIM * E_DIM);
    int r = idx - o * (H_DIM * E_DIM);
    const float* W = (o == 0) ? Wq : (o == 1 ? Wk : Wv);
    float4 v = *(const float4*)&W[r];
    uint32_t h0, l0, h1, l1;
    split2(v.x, v.y, h0, l0);
    split2(v.z, v.w, h1, l1);
    *(uint2*)&g_wh[idx] = make_uint2(h0, h1);
    *(uint2*)&g_wl[idx] = make_uint2(l0, l1);
}

// ---------------------------------------------------------------------------
// Kernel 1: QKV projection, bf16x3 warp MMA, cp.async double-buffered.
// grid=(256,3), block=128 (4 warps x 16 rows).  BM=64, BN=128, BK=64.
// Stage (bf16 elems, stride 72): Xh 0, Xl 4608, Wh 9216, Wl 18432; 27648
// elems = 55296 B per stage x2 = 110592 B.
// ---------------------------------------------------------------------------
#define QAST 72
#define QSTG 27648
#define QKV_SMEM (2 * 55296)

__global__ __launch_bounds__(128)
void qkv_mma_kernel()
{
    extern __shared__ __align__(16) __nv_bfloat16 sm_q[];
    const int tid  = threadIdx.x;
    const int lane = tid & 31;
    const int wid  = tid >> 5;
    const int m0   = blockIdx.x * 64;
    const int o    = blockIdx.y;
    const size_t wbase = (size_t)o * H_DIM * E_DIM;

    float c[16][4];
#pragma unroll
    for (int j = 0; j < 16; j++)
#pragma unroll
        for (int i = 0; i < 4; i++) c[j][i] = 0.f;

    // --- async stage issue for chunk cc into stage s ---
    auto issue = [&](int cc, int s) {
        __nv_bfloat16* st = sm_q + s * QSTG;
        uint32_t sb = smem_u32(st);
        const int k0 = cc * 64;
#pragma unroll
        for (int i = 0; i < 4; i++) {
            int idx = tid + i * 128;           // 512 x 16B  (X: 64 rows x 128B)
            int row = idx >> 3, c16 = idx & 7;
            size_t g = (size_t)(m0 + row) * E_DIM + k0 + c16 * 8;
            uint32_t d = sb + (row * QAST + c16 * 8) * 2;
            cp16(d,            &g_xh[g]);
            cp16(d + 9216,     &g_xl[g]);      // +4608 elems
        }
#pragma unroll
        for (int i = 0; i < 8; i++) {
            int idx = tid + i * 128;           // 1024 x 16B (W: 128 rows x 128B)
            int row = idx >> 3, c16 = idx & 7;
            size_t g = wbase + (size_t)row * E_DIM + k0 + c16 * 8;
            uint32_t d = sb + ((9216 + row * QAST + c16 * 8)) * 2;
            cp16(d,            &g_wh[g]);
            cp16(d + 18432,    &g_wl[g]);      // +9216 elems
        }
    };

    issue(0, 0); CP_COMMIT();

    for (int cc = 0; cc < 12; cc++) {
        if (cc < 11) { issue(cc + 1, (cc + 1) & 1); CP_COMMIT(); }
        if (cc < 11) CP_WAIT1(); else CP_WAIT0();
        __syncthreads();

        __nv_bfloat16* st = sm_q + (cc & 1) * QSTG;
        const uint32_t xh_base = smem_u32(st);
        __nv_bfloat16* Wh = st + 9216;
#pragma unroll
        for (int kd = 0; kd < 4; kd++) {
            uint32_t ah[4], al[4];
            uint32_t aaddr = xh_base +
                ((wid * 16 + (lane & 15)) * QAST + kd * 16 + ((lane >> 4) << 3)) * 2;
            ldmx4(ah, aaddr);
            ldmx4(al, aaddr + 9216);
#pragma unroll
            for (int j = 0; j < 16; j++) {
                const __nv_bfloat16* bp =
                    &Wh[(j * 8 + (lane >> 2)) * QAST + kd * 16 + (lane & 3) * 2];
                uint32_t bh0 = *(const uint32_t*)bp;
                uint32_t bh1 = *(const uint32_t*)(bp + 8);
                uint32_t bl0 = *(const uint32_t*)(bp + 9216);
                uint32_t bl1 = *(const uint32_t*)(bp + 9224);
                mma16816(c[j], ah[0], ah[1], ah[2], ah[3], bh0, bh1);
                mma16816(c[j], ah[0], ah[1], ah[2], ah[3], bl0, bl1);
                mma16816(c[j], al[0], al[1], al[2], al[3], bh0, bh1);
            }
        }
        __syncthreads();
    }

    // --- epilogue: split accumulators to hi/lo bf16 ---
    const float sc = (o == 0) ? 0.0883883476483184f : 1.f;   // 1/sqrt(128) on q
    __nv_bfloat16* oh = (o == 0) ? g_qh : (o == 1 ? g_kh : g_vh);
    __nv_bfloat16* ol = (o == 0) ? g_ql : (o == 1 ? g_kl : g_vl);
    const int grp = lane >> 2;
    const size_t r0 = (size_t)(m0 + wid * 16 + grp) * H_DIM;
    const size_t r1 = r0 + 8 * H_DIM;
#pragma unroll
    for (int j = 0; j < 16; j++) {
        int col = j * 8 + (lane & 3) * 2;
        uint32_t h, l;
        split2(c[j][0] * sc, c[j][1] * sc, h, l);
        *(uint32_t*)&oh[r0 + col] = h;
        *(uint32_t*)&ol[r0 + col] = l;
        split2(c[j][2] * sc, c[j][3] * sc, h, l);
        *(uint32_t*)&oh[r1 + col] = h;
        *(uint32_t*)&ol[r1 + col] = l;
    }
}

// ---------------------------------------------------------------------------
// Kernel 2: causal flash attention, bf16x3 warp MMA, cp.async K/V pipeline.
// grid=(32,8) long-first, block=128 (4 warps x 16 q-rows).  QT=KT=64.
// Smem (bf16 elems, stride 136): Qh 0, Ql 8704; then 2 KV stages of
// {Kh 0, Kl 8704, Vh 17408, Vl 26112} (34816 elems each).  174080 B total.
// ---------------------------------------------------------------------------
#define AST 136
#define KVSTG 34816
#define ATT_SMEM 174080

__global__ __launch_bounds__(128)
void attn_mma_kernel(float* __restrict__ out)
{
    extern __shared__ __align__(16) __nv_bfloat16 sm_a[];
    __nv_bfloat16* Qh = sm_a;

    const int tid  = threadIdx.x;
    const int lane = tid & 31;
    const int wid  = tid >> 5;
    const int b    = blockIdx.y;
    const int qt   = 31 - (int)blockIdx.x;     // long blocks first
    const int q0   = qt * 64;

    const uint32_t qh_base = smem_u32(Qh);

    // --- issue K/V tile kt into stage s (cp.async) ---
    auto issue_kv = [&](int kt, int s) {
        uint32_t kb = smem_u32(sm_a + 17408 + s * KVSTG);
#pragma unroll
        for (int i = 0; i < 8; i++) {
            int idx = tid + i * 128;           // 1024 x (4 x 16B)
            int row = idx >> 4, c8 = idx & 15;
            size_t g = ((size_t)b * S_LEN + kt * 64 + row) * H_DIM + c8 * 8;
            uint32_t d = kb + (row * AST + c8 * 8) * 2;
            cp16(d,         &g_kh[g]);
            cp16(d + 17408, &g_kl[g]);
            cp16(d + 34816, &g_vh[g]);
            cp16(d + 52224, &g_vl[g]);
        }
    };

    issue_kv(0, 0); CP_COMMIT();

    // --- stage Q (hi/lo), persists across kv tiles ---
#pragma unroll
    for (int i = 0; i < 8; i++) {
        int idx = tid + i * 128;
        int row = idx >> 4, c8 = idx & 15;
        size_t g = ((size_t)b * S_LEN + q0 + row) * H_DIM + c8 * 8;
        *(uint4*)&Qh[row * AST + c8 * 8]        = *(const uint4*)&g_qh[g];
        *(uint4*)&Qh[8704 + row * AST + c8 * 8] = *(const uint4*)&g_ql[g];
    }

    float o_[16][4];
#pragma unroll
    for (int d = 0; d < 16; d++)
#pragma unroll
        for (int i = 0; i < 4; i++) o_[d][i] = 0.f;
    float lsum0 = 0.f, lsum1 = 0.f;

    const int colb = (lane & 3) * 2;
    const int r0l  = wid * 16 + (lane >> 2);
    const int r1l  = r0l + 8;

    for (int kt = 0; kt <= qt; kt++) {
        if (kt < qt) { issue_kv(kt + 1, (kt + 1) & 1); CP_COMMIT(); }
        if (kt < qt) CP_WAIT1(); else CP_WAIT0();
        __syncthreads();

        __nv_bfloat16* Kb = sm_a + 17408 + (kt & 1) * KVSTG;
        __nv_bfloat16* Vb = Kb + 17408;
        const uint32_t vh_base = smem_u32(Vb);

        // --- S = Q K^T ---
        float s[8][4];
#pragma unroll
        for (int j = 0; j < 8; j++)
#pragma unroll
            for (int i = 0; i < 4; i++) s[j][i] = 0.f;

#pragma unroll
        for (int kd = 0; kd < 8; kd++) {
            uint32_t ah[4], al[4];
            uint32_t aaddr = qh_base +
                ((wid * 16 + (lane & 15)) * AST + kd * 16 + ((lane >> 4) << 3)) * 2;
            ldmx4(ah, aaddr);
            ldmx4(al, aaddr + 17408);
#pragma unroll
            for (int j = 0; j < 8; j++) {
                const __nv_bfloat16* bp =
                    &Kb[(j * 8 + (lane >> 2)) * AST + kd * 16 + (lane & 3) * 2];
                uint32_t bh0 = *(const uint32_t*)bp;
                uint32_t bh1 = *(const uint32_t*)(bp + 8);
                uint32_t bl0 = *(const uint32_t*)(bp + 8704);
                uint32_t bl1 = *(const uint32_t*)(bp + 8712);
                mma16816(s[j], ah[0], ah[1], ah[2], ah[3], bh0, bh1);
                mma16816(s[j], ah[0], ah[1], ah[2], ah[3], bl0, bl1);
                mma16816(s[j], al[0], al[1], al[2], al[3], bh0, bh1);
            }
        }

        // --- exp (+ causal mask on diagonal tile), row sums ---
        const bool diag = (kt == qt);
        float rs0 = 0.f, rs1 = 0.f;
#pragma unroll
        for (int j = 0; j < 8; j++) {
            int cc = j * 8 + colb;
            float e0 = __expf(s[j][0]);
            float e1 = __expf(s[j][1]);
            float e2 = __expf(s[j][2]);
            float e3 = __expf(s[j][3]);
            if (diag) {
                if (cc     > r0l) e0 = 0.f;
                if (cc + 1 > r0l) e1 = 0.f;
                if (cc     > r1l) e2 = 0.f;
                if (cc + 1 > r1l) e3 = 0.f;
            }
            s[j][0] = e0; s[j][1] = e1; s[j][2] = e2; s[j][3] = e3;
            rs0 += e0 + e1;
            rs1 += e2 + e3;
        }
        rs0 += __shfl_xor_sync(0xffffffffu, rs0, 1);
        rs0 += __shfl_xor_sync(0xffffffffu, rs0, 2);
        rs1 += __shfl_xor_sync(0xffffffffu, rs1, 1);
        rs1 += __shfl_xor_sync(0xffffffffu, rs1, 2);
        lsum0 += rs0;
        lsum1 += rs1;

        // --- O += P V.  P A-frags built in-register from S C-frags. ---
#pragma unroll
        for (int j2 = 0; j2 < 4; j2++) {
            uint32_t ph[4], pl[4];
            split2(s[2 * j2][0],     s[2 * j2][1],     ph[0], pl[0]);
            split2(s[2 * j2][2],     s[2 * j2][3],     ph[1], pl[1]);
            split2(s[2 * j2 + 1][0], s[2 * j2 + 1][1], ph[2], pl[2]);
            split2(s[2 * j2 + 1][2], s[2 * j2 + 1][3], ph[3], pl[3]);
#pragma unroll
            for (int dn = 0; dn < 16; dn++) {
                uint32_t vaddr = vh_base +
                    ((j2 * 16 + (lane & 15)) * AST + dn * 8) * 2;
                uint32_t vh0, vh1, vl0, vl1;
                ldmx2t(vh0, vh1, vaddr);
                ldmx2t(vl0, vl1, vaddr + 17408);
                mma16816(o_[dn], ph[0], ph[1], ph[2], ph[3], vh0, vh1);
                mma16816(o_[dn], ph[0], ph[1], ph[2], ph[3], vl0, vl1);
                mma16816(o_[dn], pl[0], pl[1], pl[2], pl[3], vh0, vh1);
            }
        }
        __syncthreads();
    }

    // --- epilogue ---
    const float inv0 = 1.f / lsum0;
    const float inv1 = 1.f / lsum1;
    const size_t gr0 = ((size_t)b * S_LEN + q0 + r0l) * H_DIM;
    const size_t gr1 = gr0 + 8 * H_DIM;
#pragma unroll
    for (int dn = 0; dn < 16; dn++) {
        int col = dn * 8 + colb;
        *(float2*)&out[gr0 + col] = make_float2(o_[dn][0] * inv0, o_[dn][1] * inv0);
        *(float2*)&out[gr1 + col] = make_float2(o_[dn][2] * inv1, o_[dn][3] * inv1);
    }
}

// ---------------------------------------------------------------------------
extern "C" void kernel_launch(void* const* d_in, const int* in_sizes, int n_in,
                              void* d_out, int out_size)
{
    const float* X    = (const float*)d_in[0];
    const float* mask = (const float*)d_in[1];
    const float* Wq   = (const float*)d_in[2];
    const float* Wk   = (const float*)d_in[3];
    const float* Wv   = (const float*)d_in[4];
    float* out        = (float*)d_out;

    split_x_kernel<<<M_TOTAL * E_DIM / 4 / 256, 256>>>(X, mask);
    split_w_kernel<<<3 * H_DIM * E_DIM / 4 / 256, 256>>>(Wq, Wk, Wv);

    cudaFuncSetAttribute(qkv_mma_kernel,
                         cudaFuncAttributeMaxDynamicSharedMemorySize, QKV_SMEM);
    dim3 g1(M_TOTAL / 64, 3);
    qkv_mma_kernel<<<g1, 128, QKV_SMEM>>>();

    cudaFuncSetAttribute(attn_mma_kernel,
                         cudaFuncAttributeMaxDynamicSharedMemorySize, ATT_SMEM);
    dim3 g2(32, B_SZ);
    attn_mma_kernel<<<g2, 128, ATT_SMEM>>>(out);
}